// round 14
// baseline (speedup 1.0000x reference)
#include <cuda_runtime.h>
#include <math.h>
#include <stdint.h>

// Problem constants
#define BATCH 64
#define LDIM  1024
#define FFDIM 8192
#define HDIM  256
#define RDIM  4
#define EPSC  1e-4f

// Scratch
__device__ float    g_mod[BATCH * FFDIM];   // 2 MB, layout [b][f]
__device__ uint32_t g_xh[BATCH * 512];
__device__ uint32_t g_xl[BATCH * 512];
__device__ float    g_abs[128 * 64];        // per-(GEMM CTA, b) |mod| partials
__device__ float    g_scale[BATCH * 4];
__device__ float    g_weff[RDIM];
__device__ float    g_beff;
__device__ float    g_magpart[BATCH * 16];
__device__ float4   g_pkm[65536];           // (wm0, wm1, A1re, A1im)
__device__ float4   g_pkf1[65536];          // (wm0, wm1, wm2, wm3)
__device__ float4   g_pkf2[65536];          // (A0re, A0im, A1re, A1im)

// ---------------------------------------------------------------------------
// fp16 scaled-split helpers: v = h + 2^-10 * l'
// ---------------------------------------------------------------------------
__device__ __forceinline__ void f16split(float v, uint16_t& h, uint16_t& l)
{
    uint16_t hh;
    asm("cvt.rn.f16.f32 %0, %1;" : "=h"(hh) : "f"(v));
    float hf;
    asm("cvt.f32.f16 %0, %1;" : "=f"(hf) : "h"(hh));
    float r = (v - hf) * 1024.0f;
    asm("cvt.rn.f16.f32 %0, %1;" : "=h"(l) : "f"(r));
    h = hh;
}
__device__ __forceinline__ uint32_t packh(uint16_t a, uint16_t b)
{
    uint32_t w;
    asm("mov.b32 %0, {%1, %2};" : "=r"(w) : "h"(a), "h"(b));
    return w;
}
__device__ __forceinline__ void split4(float4 v, uint32_t& h01, uint32_t& h23,
                                       uint32_t& l01, uint32_t& l23)
{
    uint16_t h0, h1, h2, h3, l0, l1, l2, l3;
    f16split(v.x, h0, l0);
    f16split(v.y, h1, l1);
    f16split(v.z, h2, l2);
    f16split(v.w, h3, l3);
    h01 = packh(h0, h1); h23 = packh(h2, h3);
    l01 = packh(l0, l1); l23 = packh(l2, l3);
}

__device__ __forceinline__ void mma16(float* d, const uint32_t* a, const uint32_t* b)
{
    asm volatile(
        "mma.sync.aligned.m16n8k16.row.col.f32.f16.f16.f32 "
        "{%0,%1,%2,%3}, {%4,%5,%6,%7}, {%8,%9}, {%0,%1,%2,%3};"
        : "+f"(d[0]), "+f"(d[1]), "+f"(d[2]), "+f"(d[3])
        : "r"(a[0]), "r"(a[1]), "r"(a[2]), "r"(a[3]), "r"(b[0]), "r"(b[1]));
}

// ---------------------------------------------------------------------------
// Kernel P: pack per-pixel weight data. grid 256 x 256 thr.
// ---------------------------------------------------------------------------
__global__ void __launch_bounds__(256)
k_pack(const float* __restrict__ ws, const float* __restrict__ wm)
{
    const int pix = blockIdx.x * 256 + threadIdx.x;
    float  w0 = wm[pix];
    float  w1 = wm[65536 + pix];
    float  w2 = wm[131072 + pix];
    float  w3 = wm[196608 + pix];
    float2 A0 = *reinterpret_cast<const float2*>(&ws[2 * pix]);
    float2 A1 = *reinterpret_cast<const float2*>(&ws[131072 + 2 * pix]);
    g_pkm[pix]  = make_float4(w0, w1, A1.x, A1.y);
    g_pkf1[pix] = make_float4(w0, w1, w2, w3);
    g_pkf2[pix] = make_float4(A0.x, A0.y, A1.x, A1.y);
}

// ---------------------------------------------------------------------------
// Kernel 0: pre-split x into packed fp16x2 (hi, scaled-lo). 64 x 256.
// ---------------------------------------------------------------------------
__global__ void __launch_bounds__(256)
k_xsplit(const float* __restrict__ x)
{
    const int idx = blockIdx.x * 256 + threadIdx.x;
    float4 v = reinterpret_cast<const float4*>(x)[idx];
    uint32_t h01, h23, l01, l23;
    split4(v, h01, h23, l01, l23);
    reinterpret_cast<uint2*>(g_xh)[idx] = make_uint2(h01, h23);
    reinterpret_cast<uint2*>(g_xl)[idx] = make_uint2(l01, l23);
}

// ---------------------------------------------------------------------------
// Kernel 1: fused GEMM pair + silu (R10 core) + fused |mod| partial sums.
// ---------------------------------------------------------------------------
#define WSTR   20
#define TILE_W (64 * WSTR)
#define ST_WTH 0
#define ST_WTL (1 * TILE_W)
#define ST_WGH (2 * TILE_W)
#define ST_WGL (3 * TILE_W)
#define ST_XH  (4 * TILE_W)
#define ST_XL  (5 * TILE_W)
#define STAGE_WORDS (6 * TILE_W)
#define GEMM_SMEM_BYTES (2 * STAGE_WORDS * 4)   // 61440 B

__global__ void __launch_bounds__(256, 1)
k_gemm_mma(const float* __restrict__ Wt,
           const float* __restrict__ Wg)
{
    extern __shared__ uint32_t smw[];
    const int t    = threadIdx.x;
    const int warp = t >> 5, lane = t & 31;
    const int gid  = lane >> 2, tig = lane & 3;
    const int mb   = (warp & 3) * 16;
    const int nb   = (warp >> 2) * 32;
    const int f0   = blockIdx.x * 64;

    const float4* Wt4 = reinterpret_cast<const float4*>(Wt);
    const float4* Wg4 = reinterpret_cast<const float4*>(Wg);
    const uint4*  Xh4 = reinterpret_cast<const uint4*>(g_xh);
    const uint4*  Xl4 = reinterpret_cast<const uint4*>(g_xl);

    const int xrow = t >> 2;
    const int xc   = t & 3;

    float acc1[2][4][4], acc2[2][4][4];
#pragma unroll
    for (int g = 0; g < 2; g++)
#pragma unroll
        for (int j = 0; j < 4; j++)
#pragma unroll
            for (int c = 0; c < 4; c++) { acc1[g][j][c] = 0.f; acc2[g][j][c] = 0.f; }

    float4 wtp[2], wgp[2];
    uint4  xhq, xlq;
    {
#pragma unroll
        for (int q = 0; q < 2; q++) {
            int idx = q * 256 + t, row = idx >> 3, col = idx & 7;
            wtp[q] = Wt4[(size_t)(f0 + row) * 256 + col];
            wgp[q] = Wg4[(size_t)(f0 + row) * 256 + col];
        }
        xhq = Xh4[xrow * 128 + xc];
        xlq = Xl4[xrow * 128 + xc];
    }

    for (int kt = 0; kt < 32; ++kt) {
        uint32_t* st = smw + (kt & 1) * STAGE_WORDS;
#pragma unroll
        for (int q = 0; q < 2; q++) {
            int idx = q * 256 + t, row = idx >> 3, col = idx & 7;
            int off = row * WSTR + col * 2;
            uint32_t h01, h23, l01, l23;
            split4(wtp[q], h01, h23, l01, l23);
            *reinterpret_cast<uint2*>(&st[ST_WTH + off]) = make_uint2(h01, h23);
            *reinterpret_cast<uint2*>(&st[ST_WTL + off]) = make_uint2(l01, l23);
            split4(wgp[q], h01, h23, l01, l23);
            *reinterpret_cast<uint2*>(&st[ST_WGH + off]) = make_uint2(h01, h23);
            *reinterpret_cast<uint2*>(&st[ST_WGL + off]) = make_uint2(l01, l23);
        }
        *reinterpret_cast<uint4*>(&st[ST_XH + xrow * WSTR + xc * 4]) = xhq;
        *reinterpret_cast<uint4*>(&st[ST_XL + xrow * WSTR + xc * 4]) = xlq;
        __syncthreads();

        if (kt + 1 < 32) {
            const size_t ko = (size_t)(kt + 1) * 8;
#pragma unroll
            for (int q = 0; q < 2; q++) {
                int idx = q * 256 + t, row = idx >> 3, col = idx & 7;
                wtp[q] = Wt4[(size_t)(f0 + row) * 256 + ko + col];
                wgp[q] = Wg4[(size_t)(f0 + row) * 256 + ko + col];
            }
            xhq = Xh4[xrow * 128 + (kt + 1) * 4 + xc];
            xlq = Xl4[xrow * 128 + (kt + 1) * 4 + xc];
        }

#pragma unroll
        for (int ks = 0; ks < 2; ++ks) {
            const int kb = ks * 8;
            uint32_t Ah[2][4], Al[2][4], Bh[4][2], Bl[4][2];
#pragma unroll
            for (int g = 0; g < 2; ++g) {
                const uint32_t* th = st + (g ? ST_WGH : ST_WTH);
                const uint32_t* tl = st + (g ? ST_WGL : ST_WTL);
                int r0 = (mb + gid) * WSTR + kb + tig;
                int r1 = r0 + 8 * WSTR;
                Ah[g][0] = th[r0];     Ah[g][1] = th[r1];
                Ah[g][2] = th[r0 + 4]; Ah[g][3] = th[r1 + 4];
                Al[g][0] = tl[r0];     Al[g][1] = tl[r1];
                Al[g][2] = tl[r0 + 4]; Al[g][3] = tl[r1 + 4];
            }
#pragma unroll
            for (int j = 0; j < 4; ++j) {
                int bb = (nb + j * 8 + gid) * WSTR + kb + tig;
                Bh[j][0] = st[ST_XH + bb]; Bh[j][1] = st[ST_XH + bb + 4];
                Bl[j][0] = st[ST_XL + bb]; Bl[j][1] = st[ST_XL + bb + 4];
            }
#pragma unroll
            for (int g = 0; g < 2; ++g)
#pragma unroll
                for (int j = 0; j < 4; ++j) {
                    mma16(acc1[g][j], Ah[g], Bh[j]);
                    mma16(acc2[g][j], Ah[g], Bl[j]);
                    mma16(acc2[g][j], Al[g], Bh[j]);
                }
        }
    }

    __syncthreads();
    float* sOut = reinterpret_cast<float*>(smw);   // 64 (b) x 68-stride (f)
#pragma unroll
    for (int j = 0; j < 4; ++j)
#pragma unroll
        for (int c = 0; c < 4; ++c) {
            float tv = fmaf(acc2[0][j][c], 1.0f / 1024.0f, acc1[0][j][c]);
            float gv = fmaf(acc2[1][j][c], 1.0f / 1024.0f, acc1[1][j][c]);
            float o  = tv * __fdividef(gv, 1.0f + __expf(-gv));
            int fl = mb + gid + ((c >> 1) << 3);
            int bl = nb + j * 8 + 2 * tig + (c & 1);
            sOut[bl * 68 + fl] = o;
        }
    __syncthreads();

#pragma unroll
    for (int v = 0; v < 4; ++v) {
        int idx = v * 256 + t;
        int row = idx >> 4, q = idx & 15;
        float4 val = *reinterpret_cast<const float4*>(sOut + row * 68 + q * 4);
        *reinterpret_cast<float4*>(&g_mod[(size_t)row * FFDIM + f0 + q * 4]) = val;
        // fused |mod| partial: 16 lanes share a row
        float s = fabsf(val.x) + fabsf(val.y) + fabsf(val.z) + fabsf(val.w);
        s += __shfl_xor_sync(0xFFFFFFFFu, s, 8);
        s += __shfl_xor_sync(0xFFFFFFFFu, s, 4);
        s += __shfl_xor_sync(0xFFFFFFFFu, s, 2);
        s += __shfl_xor_sync(0xFFFFFFFFu, s, 1);
        if (q == 0) g_abs[blockIdx.x * 64 + row] = s;
    }
}

// ---------------------------------------------------------------------------
// Kernel 2: reduce GEMM |mod| partials -> scales. 256 blocks x 32 thr.
// ---------------------------------------------------------------------------
__global__ void __launch_bounds__(32)
k_scale(const float* __restrict__ conv_w,
        const float* __restrict__ conv_b)
{
    const int g = blockIdx.x;                 // g = b*4 + k
    const int t = threadIdx.x;
    const int b = g >> 2, k = g & 3;
    float s = g_abs[(k * 32 + t) * 64 + b];
#pragma unroll
    for (int o = 16; o > 0; o >>= 1) s += __shfl_xor_sync(0xFFFFFFFFu, s, o);
    if (t == 0)
        g_scale[g] = rsqrtf(s * (1.0f / 2048.0f) + EPSC);

    if (g == 0) {
        if (t < RDIM) {
            float w = 0.f;
#pragma unroll
            for (int i = 0; i < RDIM; i++) w += conv_w[i * RDIM + t];
            g_weff[t] = w;
        }
        if (t == RDIM) {
            float bsum = 0.f;
#pragma unroll
            for (int i = 0; i < RDIM; i++) bsum += conv_b[i];
            g_beff = bsum;
        }
    }
}

// ---------------------------------------------------------------------------
// Block reduction helper (256 threads)
// ---------------------------------------------------------------------------
__device__ __forceinline__ float block_reduce_256(float v, float* sh)
{
#pragma unroll
    for (int o = 16; o > 0; o >>= 1) v += __shfl_xor_sync(0xFFFFFFFFu, v, o);
    int w = threadIdx.x >> 5;
    if ((threadIdx.x & 31) == 0) sh[w] = v;
    __syncthreads();
    if (threadIdx.x < 8) {
        v = sh[threadIdx.x];
#pragma unroll
        for (int o = 4; o > 0; o >>= 1) v += __shfl_xor_sync(0x000000FFu, v, o);
    }
    return v;
}

// ---------------------------------------------------------------------------
// Kernel 3: per-batch magnitude partial sums. 2 batches per block.
// grid (16, 32), 256 thr. Shared pkm load serves both batches.
// ---------------------------------------------------------------------------
__global__ void __launch_bounds__(256)
k_mag(const float* __restrict__ ws, const float* __restrict__ wm)
{
    __shared__ float4 wa4[2][16][2];   // [bb][il][k]
    __shared__ float  sh[8];

    const int b0 = blockIdx.y * 2;
    const int i0 = blockIdx.x * 16;
    const int t  = threadIdx.x;

    {
        int bb = t >> 7, u = t & 127;
        int k = u >> 6, r = (u >> 4) & 3, il = u & 15;
        reinterpret_cast<float*>(wa4)[bb * 128 + il * 8 + k * 4 + r] =
            g_weff[r] * g_scale[(b0 + bb) * 4 + k]
            * g_mod[(size_t)(b0 + bb) * FFDIM + k * 2048 + r * 512 + (i0 + il)];
    }

    float sb[2][2][4];
#pragma unroll
    for (int bb = 0; bb < 2; bb++)
#pragma unroll
        for (int k = 0; k < 2; k++) {
            float sc = g_scale[(b0 + bb) * 4 + k];
#pragma unroll
            for (int r = 0; r < 4; r++)
                sb[bb][k][r] = sc * g_mod[(size_t)(b0 + bb) * FFDIM
                                          + k * 2048 + r * 512 + HDIM + t];
        }
    __syncthreads();

    const float be = g_beff;
    float sum0 = 0.f, sum1 = 0.f;

    float4 pk = g_pkm[(i0 << 8) + t];
#pragma unroll
    for (int il = 0; il < 16; il++) {
        float4 pkn;
        if (il < 15) pkn = g_pkm[((i0 + il + 1) << 8) + t];
#pragma unroll
        for (int bb = 0; bb < 2; bb++) {
            float4 w0 = wa4[bb][il][0];
            float4 w1 = wa4[bb][il][1];
            float m0 = be, m1 = be;
            m0 = fmaf(w0.x, sb[bb][0][0], m0); m0 = fmaf(w0.y, sb[bb][0][1], m0);
            m0 = fmaf(w0.z, sb[bb][0][2], m0); m0 = fmaf(w0.w, sb[bb][0][3], m0);
            m1 = fmaf(w1.x, sb[bb][1][0], m1); m1 = fmaf(w1.y, sb[bb][1][1], m1);
            m1 = fmaf(w1.z, sb[bb][1][2], m1); m1 = fmaf(w1.w, sb[bb][1][3], m1);
            m0 *= pk.x;
            m1 *= pk.y;
            float re = pk.z * m0 - pk.w * m1;
            float im = pk.z * m1 - pk.w * m0;
            float v = sqrtf(fmaf(re, re, fmaf(im, im, EPSC)));
            if (bb == 0) sum0 += v; else sum1 += v;
        }
        pk = pkn;
    }
    sum0 = block_reduce_256(sum0, sh);
    __syncthreads();
    float s0keep = sum0;
    sum1 = block_reduce_256(sum1, sh);
    if (t == 0) {
        g_magpart[b0 * 16 + blockIdx.x]       = s0keep;
        g_magpart[(b0 + 1) * 16 + blockIdx.x] = sum1;
    }
}

// ---------------------------------------------------------------------------
// Kernel 4: final output. 2 batches per block. grid (16, 32), 256 thr.
// ---------------------------------------------------------------------------
__global__ void __launch_bounds__(256)
k_final(const float* __restrict__ ws, const float* __restrict__ wm,
        float* __restrict__ out)
{
    __shared__ float4 wa4[2][16][4];   // [bb][il][k]

    const int b0 = blockIdx.y * 2;
    const int i0 = blockIdx.x * 16;
    const int t  = threadIdx.x;

#pragma unroll
    for (int q = 0; q < 2; q++) {
        int idx = t + q * 256;
        int bb = idx >> 8, u = idx & 255;
        int k = u >> 6, r = (u >> 4) & 3, il = u & 15;
        reinterpret_cast<float*>(wa4)[bb * 256 + il * 16 + k * 4 + r] =
            g_weff[r] * g_scale[(b0 + bb) * 4 + k]
            * g_mod[(size_t)(b0 + bb) * FFDIM + k * 2048 + r * 512 + (i0 + il)];
    }

    float sbv[2][4][4];
#pragma unroll
    for (int bb = 0; bb < 2; bb++)
#pragma unroll
        for (int k = 0; k < 4; k++) {
            float sc = g_scale[(b0 + bb) * 4 + k];
#pragma unroll
            for (int r = 0; r < 4; r++)
                sbv[bb][k][r] = sc * g_mod[(size_t)(b0 + bb) * FFDIM
                                           + k * 2048 + r * 512 + HDIM + t];
        }
    __syncthreads();

    float inv[2];
#pragma unroll
    for (int bb = 0; bb < 2; bb++) {
        float msum = 0.f;
#pragma unroll
        for (int q = 0; q < 16; q++) msum += g_magpart[(b0 + bb) * 16 + q];
        inv[bb] = rsqrtf(msum * (1.0f / 65536.0f) + EPSC);
    }
    const float be = g_beff;

    float4 p1 = g_pkf1[(i0 << 8) + t];
    float4 p2 = g_pkf2[(i0 << 8) + t];
#pragma unroll
    for (int il = 0; il < 16; il++) {
        float4 p1n, p2n;
        if (il < 15) {
            const int pixn = ((i0 + il + 1) << 8) + t;
            p1n = g_pkf1[pixn];
            p2n = g_pkf2[pixn];
        }
        const int pix = ((i0 + il) << 8) + t;
#pragma unroll
        for (int bb = 0; bb < 2; bb++) {
            float m[4];
#pragma unroll
            for (int k = 0; k < 4; k++) {
                float4 wk = wa4[bb][il][k];
                float acc = be;
                acc = fmaf(wk.x, sbv[bb][k][0], acc);
                acc = fmaf(wk.y, sbv[bb][k][1], acc);
                acc = fmaf(wk.z, sbv[bb][k][2], acc);
                acc = fmaf(wk.w, sbv[bb][k][3], acc);
                m[k] = acc;
            }
            m[0] *= p1.x; m[1] *= p1.y; m[2] *= p1.z; m[3] *= p1.w;
            float re = p2.z * m[0] - p2.w * m[1];
            float im = p2.z * m[1] - p2.w * m[0];
            float mwre = fmaf(re, inv[bb], p2.x);
            float mwim = fmaf(im, inv[bb], p2.y);
            float den = sqrtf(fmaf(m[2], m[2], fmaf(m[3], m[3], EPSC)));
            out[((size_t)(b0 + bb) << 16) + pix] =
                __fdividef(fmaf(mwre, m[2], mwim * m[3]), den);
        }
        p1 = p1n; p2 = p2n;
    }
}

// ---------------------------------------------------------------------------
// Launch
// ---------------------------------------------------------------------------
extern "C" void kernel_launch(void* const* d_in, const int* in_sizes, int n_in,
                              void* d_out, int out_size)
{
    const float* x      = (const float*)d_in[0];
    const float* Wt     = (const float*)d_in[1];
    const float* Wg     = (const float*)d_in[2];
    const float* ws     = (const float*)d_in[3];
    const float* wm     = (const float*)d_in[4];
    const float* conv_w = (const float*)d_in[5];
    const float* conv_b = (const float*)d_in[6];
    float* out = (float*)d_out;

    cudaFuncSetAttribute(k_gemm_mma,
                         cudaFuncAttributeMaxDynamicSharedMemorySize,
                         GEMM_SMEM_BYTES);

    k_xsplit<<<64, 256>>>(x);
    k_pack<<<256, 256>>>(ws, wm);
    k_gemm_mma<<<FFDIM / 64, 256, GEMM_SMEM_BYTES>>>(Wt, Wg);
    k_scale<<<BATCH * 4, 32>>>(conv_w, conv_b);
    k_mag<<<dim3(16, 32), 256>>>(ws, wm);
    k_final<<<dim3(16, 32), 256>>>(ws, wm, out);
}

// round 15
// speedup vs baseline: 1.0661x; 1.0661x over previous
#include <cuda_runtime.h>
#include <math.h>
#include <stdint.h>

// Problem constants
#define BATCH 64
#define LDIM  1024
#define FFDIM 8192
#define HDIM  256
#define RDIM  4
#define EPSC  1e-4f

// Scratch
__device__ float    g_mod[BATCH * FFDIM];   // 2 MB, layout [b][f]
__device__ uint32_t g_xh[BATCH * 512];
__device__ uint32_t g_xl[BATCH * 512];
__device__ float    g_abs[128 * 64];        // per-(GEMM CTA, b) |mod| partials
__device__ float    g_magpart[BATCH * 16];
__device__ float4   g_pkm[65536];           // (wm0, wm1, A1re, A1im)
__device__ float4   g_pkf1[65536];          // (wm0, wm1, wm2, wm3)
__device__ float4   g_pkf2[65536];          // (A0re, A0im, A1re, A1im)

// ---------------------------------------------------------------------------
// fp16 scaled-split helpers: v = h + 2^-10 * l'
// ---------------------------------------------------------------------------
__device__ __forceinline__ void f16split(float v, uint16_t& h, uint16_t& l)
{
    uint16_t hh;
    asm("cvt.rn.f16.f32 %0, %1;" : "=h"(hh) : "f"(v));
    float hf;
    asm("cvt.f32.f16 %0, %1;" : "=f"(hf) : "h"(hh));
    float r = (v - hf) * 1024.0f;
    asm("cvt.rn.f16.f32 %0, %1;" : "=h"(l) : "f"(r));
    h = hh;
}
__device__ __forceinline__ uint32_t packh(uint16_t a, uint16_t b)
{
    uint32_t w;
    asm("mov.b32 %0, {%1, %2};" : "=r"(w) : "h"(a), "h"(b));
    return w;
}
__device__ __forceinline__ void split4(float4 v, uint32_t& h01, uint32_t& h23,
                                       uint32_t& l01, uint32_t& l23)
{
    uint16_t h0, h1, h2, h3, l0, l1, l2, l3;
    f16split(v.x, h0, l0);
    f16split(v.y, h1, l1);
    f16split(v.z, h2, l2);
    f16split(v.w, h3, l3);
    h01 = packh(h0, h1); h23 = packh(h2, h3);
    l01 = packh(l0, l1); l23 = packh(l2, l3);
}

__device__ __forceinline__ void mma16(float* d, const uint32_t* a, const uint32_t* b)
{
    asm volatile(
        "mma.sync.aligned.m16n8k16.row.col.f32.f16.f16.f32 "
        "{%0,%1,%2,%3}, {%4,%5,%6,%7}, {%8,%9}, {%0,%1,%2,%3};"
        : "+f"(d[0]), "+f"(d[1]), "+f"(d[2]), "+f"(d[3])
        : "r"(a[0]), "r"(a[1]), "r"(a[2]), "r"(a[3]), "r"(b[0]), "r"(b[1]));
}

// ---------------------------------------------------------------------------
// Kernel PRE: blocks 0-63 split x; blocks 64-319 pack per-pixel weights.
// ---------------------------------------------------------------------------
__global__ void __launch_bounds__(256)
k_pre(const float* __restrict__ x,
      const float* __restrict__ ws, const float* __restrict__ wm)
{
    const int t = threadIdx.x;
    if (blockIdx.x < 64) {
        const int idx = blockIdx.x * 256 + t;   // 0..16383 float4s of x
        float4 v = reinterpret_cast<const float4*>(x)[idx];
        uint32_t h01, h23, l01, l23;
        split4(v, h01, h23, l01, l23);
        reinterpret_cast<uint2*>(g_xh)[idx] = make_uint2(h01, h23);
        reinterpret_cast<uint2*>(g_xl)[idx] = make_uint2(l01, l23);
    } else {
        const int pix = (blockIdx.x - 64) * 256 + t;
        float  w0 = wm[pix];
        float  w1 = wm[65536 + pix];
        float  w2 = wm[131072 + pix];
        float  w3 = wm[196608 + pix];
        float2 A0 = *reinterpret_cast<const float2*>(&ws[2 * pix]);
        float2 A1 = *reinterpret_cast<const float2*>(&ws[131072 + 2 * pix]);
        g_pkm[pix]  = make_float4(w0, w1, A1.x, A1.y);
        g_pkf1[pix] = make_float4(w0, w1, w2, w3);
        g_pkf2[pix] = make_float4(A0.x, A0.y, A1.x, A1.y);
    }
}

// ---------------------------------------------------------------------------
// Kernel 1: fused GEMM pair + silu (R10 core) + fused |mod| partial sums.
// ---------------------------------------------------------------------------
#define WSTR   20
#define TILE_W (64 * WSTR)
#define ST_WTH 0
#define ST_WTL (1 * TILE_W)
#define ST_WGH (2 * TILE_W)
#define ST_WGL (3 * TILE_W)
#define ST_XH  (4 * TILE_W)
#define ST_XL  (5 * TILE_W)
#define STAGE_WORDS (6 * TILE_W)
#define GEMM_SMEM_BYTES (2 * STAGE_WORDS * 4)   // 61440 B

__global__ void __launch_bounds__(256, 1)
k_gemm_mma(const float* __restrict__ Wt,
           const float* __restrict__ Wg)
{
    extern __shared__ uint32_t smw[];
    const int t    = threadIdx.x;
    const int warp = t >> 5, lane = t & 31;
    const int gid  = lane >> 2, tig = lane & 3;
    const int mb   = (warp & 3) * 16;
    const int nb   = (warp >> 2) * 32;
    const int f0   = blockIdx.x * 64;

    const float4* Wt4 = reinterpret_cast<const float4*>(Wt);
    const float4* Wg4 = reinterpret_cast<const float4*>(Wg);
    const uint4*  Xh4 = reinterpret_cast<const uint4*>(g_xh);
    const uint4*  Xl4 = reinterpret_cast<const uint4*>(g_xl);

    const int xrow = t >> 2;
    const int xc   = t & 3;

    float acc1[2][4][4], acc2[2][4][4];
#pragma unroll
    for (int g = 0; g < 2; g++)
#pragma unroll
        for (int j = 0; j < 4; j++)
#pragma unroll
            for (int c = 0; c < 4; c++) { acc1[g][j][c] = 0.f; acc2[g][j][c] = 0.f; }

    float4 wtp[2], wgp[2];
    uint4  xhq, xlq;
    {
#pragma unroll
        for (int q = 0; q < 2; q++) {
            int idx = q * 256 + t, row = idx >> 3, col = idx & 7;
            wtp[q] = Wt4[(size_t)(f0 + row) * 256 + col];
            wgp[q] = Wg4[(size_t)(f0 + row) * 256 + col];
        }
        xhq = Xh4[xrow * 128 + xc];
        xlq = Xl4[xrow * 128 + xc];
    }

    for (int kt = 0; kt < 32; ++kt) {
        uint32_t* st = smw + (kt & 1) * STAGE_WORDS;
#pragma unroll
        for (int q = 0; q < 2; q++) {
            int idx = q * 256 + t, row = idx >> 3, col = idx & 7;
            int off = row * WSTR + col * 2;
            uint32_t h01, h23, l01, l23;
            split4(wtp[q], h01, h23, l01, l23);
            *reinterpret_cast<uint2*>(&st[ST_WTH + off]) = make_uint2(h01, h23);
            *reinterpret_cast<uint2*>(&st[ST_WTL + off]) = make_uint2(l01, l23);
            split4(wgp[q], h01, h23, l01, l23);
            *reinterpret_cast<uint2*>(&st[ST_WGH + off]) = make_uint2(h01, h23);
            *reinterpret_cast<uint2*>(&st[ST_WGL + off]) = make_uint2(l01, l23);
        }
        *reinterpret_cast<uint4*>(&st[ST_XH + xrow * WSTR + xc * 4]) = xhq;
        *reinterpret_cast<uint4*>(&st[ST_XL + xrow * WSTR + xc * 4]) = xlq;
        __syncthreads();

        if (kt + 1 < 32) {
            const size_t ko = (size_t)(kt + 1) * 8;
#pragma unroll
            for (int q = 0; q < 2; q++) {
                int idx = q * 256 + t, row = idx >> 3, col = idx & 7;
                wtp[q] = Wt4[(size_t)(f0 + row) * 256 + ko + col];
                wgp[q] = Wg4[(size_t)(f0 + row) * 256 + ko + col];
            }
            xhq = Xh4[xrow * 128 + (kt + 1) * 4 + xc];
            xlq = Xl4[xrow * 128 + (kt + 1) * 4 + xc];
        }

#pragma unroll
        for (int ks = 0; ks < 2; ++ks) {
            const int kb = ks * 8;
            uint32_t Ah[2][4], Al[2][4], Bh[4][2], Bl[4][2];
#pragma unroll
            for (int g = 0; g < 2; ++g) {
                const uint32_t* th = st + (g ? ST_WGH : ST_WTH);
                const uint32_t* tl = st + (g ? ST_WGL : ST_WTL);
                int r0 = (mb + gid) * WSTR + kb + tig;
                int r1 = r0 + 8 * WSTR;
                Ah[g][0] = th[r0];     Ah[g][1] = th[r1];
                Ah[g][2] = th[r0 + 4]; Ah[g][3] = th[r1 + 4];
                Al[g][0] = tl[r0];     Al[g][1] = tl[r1];
                Al[g][2] = tl[r0 + 4]; Al[g][3] = tl[r1 + 4];
            }
#pragma unroll
            for (int j = 0; j < 4; ++j) {
                int bb = (nb + j * 8 + gid) * WSTR + kb + tig;
                Bh[j][0] = st[ST_XH + bb]; Bh[j][1] = st[ST_XH + bb + 4];
                Bl[j][0] = st[ST_XL + bb]; Bl[j][1] = st[ST_XL + bb + 4];
            }
#pragma unroll
            for (int g = 0; g < 2; ++g)
#pragma unroll
                for (int j = 0; j < 4; ++j) {
                    mma16(acc1[g][j], Ah[g], Bh[j]);
                    mma16(acc2[g][j], Ah[g], Bl[j]);
                    mma16(acc2[g][j], Al[g], Bh[j]);
                }
        }
    }

    __syncthreads();
    float* sOut = reinterpret_cast<float*>(smw);   // 64 (b) x 68-stride (f)
#pragma unroll
    for (int j = 0; j < 4; ++j)
#pragma unroll
        for (int c = 0; c < 4; ++c) {
            float tv = fmaf(acc2[0][j][c], 1.0f / 1024.0f, acc1[0][j][c]);
            float gv = fmaf(acc2[1][j][c], 1.0f / 1024.0f, acc1[1][j][c]);
            float o  = tv * __fdividef(gv, 1.0f + __expf(-gv));
            int fl = mb + gid + ((c >> 1) << 3);
            int bl = nb + j * 8 + 2 * tig + (c & 1);
            sOut[bl * 68 + fl] = o;
        }
    __syncthreads();

#pragma unroll
    for (int v = 0; v < 4; ++v) {
        int idx = v * 256 + t;
        int row = idx >> 4, q = idx & 15;
        float4 val = *reinterpret_cast<const float4*>(sOut + row * 68 + q * 4);
        *reinterpret_cast<float4*>(&g_mod[(size_t)row * FFDIM + f0 + q * 4]) = val;
        // fused |mod| partial: 16 lanes share a row
        float s = fabsf(val.x) + fabsf(val.y) + fabsf(val.z) + fabsf(val.w);
        s += __shfl_xor_sync(0xFFFFFFFFu, s, 8);
        s += __shfl_xor_sync(0xFFFFFFFFu, s, 4);
        s += __shfl_xor_sync(0xFFFFFFFFu, s, 2);
        s += __shfl_xor_sync(0xFFFFFFFFu, s, 1);
        if (q == 0) g_abs[blockIdx.x * 64 + row] = s;
    }
}

// ---------------------------------------------------------------------------
// Block reduction helper (256 threads)
// ---------------------------------------------------------------------------
__device__ __forceinline__ float block_reduce_256(float v, float* sh)
{
#pragma unroll
    for (int o = 16; o > 0; o >>= 1) v += __shfl_xor_sync(0xFFFFFFFFu, v, o);
    int w = threadIdx.x >> 5;
    if ((threadIdx.x & 31) == 0) sh[w] = v;
    __syncthreads();
    if (threadIdx.x < 8) {
        v = sh[threadIdx.x];
#pragma unroll
        for (int o = 4; o > 0; o >>= 1) v += __shfl_xor_sync(0x000000FFu, v, o);
    }
    return v;
}

// ---------------------------------------------------------------------------
// Kernel 3: per-batch magnitude partial sums, inline scale computation.
// grid (16, 64), 256 thr.
// ---------------------------------------------------------------------------
__global__ void __launch_bounds__(256)
k_mag(const float* __restrict__ conv_w, const float* __restrict__ conv_b)
{
    __shared__ float4 wa4[16][2];
    __shared__ float  sh[8];
    __shared__ float  s_scale[2], s_weff[4], s_beff;

    const int b  = blockIdx.y;
    const int i0 = blockIdx.x * 16;
    const int t  = threadIdx.x;

    // inline scales for k=0,1 from GEMM partials
    if (t < 64) {
        int k = t >> 5, q = t & 31;
        float s = g_abs[(k * 32 + q) * 64 + b];
#pragma unroll
        for (int o = 16; o > 0; o >>= 1) s += __shfl_xor_sync(0xFFFFFFFFu, s, o);
        if (q == 0) s_scale[k] = rsqrtf(s * (1.0f / 2048.0f) + EPSC);
    } else if (t < 68) {
        int r = t - 64;
        float w = 0.f;
#pragma unroll
        for (int i = 0; i < RDIM; i++) w += conv_w[i * RDIM + r];
        s_weff[r] = w;
    } else if (t == 68) {
        float bs = 0.f;
#pragma unroll
        for (int i = 0; i < RDIM; i++) bs += conv_b[i];
        s_beff = bs;
    }
    __syncthreads();

    if (t < 128) {
        int k = t >> 6, r = (t >> 4) & 3, il = t & 15;
        reinterpret_cast<float*>(wa4)[il * 8 + k * 4 + r] =
            s_weff[r] * s_scale[k]
            * g_mod[(size_t)b * FFDIM + k * 2048 + r * 512 + (i0 + il)];
    }

    float sb0[4], sb1[4];
    {
        float s0 = s_scale[0], s1 = s_scale[1];
#pragma unroll
        for (int r = 0; r < 4; r++) {
            sb0[r] = s0 * g_mod[(size_t)b * FFDIM + 0 * 2048 + r * 512 + HDIM + t];
            sb1[r] = s1 * g_mod[(size_t)b * FFDIM + 1 * 2048 + r * 512 + HDIM + t];
        }
    }
    __syncthreads();

    const float be = s_beff;
    float sum = 0.f;

    float4 pk = g_pkm[(i0 << 8) + t];
#pragma unroll
    for (int il = 0; il < 16; il++) {
        float4 pkn;
        if (il < 15) pkn = g_pkm[((i0 + il + 1) << 8) + t];
        float4 w0 = wa4[il][0];
        float4 w1 = wa4[il][1];
        float m0 = be, m1 = be;
        m0 = fmaf(w0.x, sb0[0], m0); m0 = fmaf(w0.y, sb0[1], m0);
        m0 = fmaf(w0.z, sb0[2], m0); m0 = fmaf(w0.w, sb0[3], m0);
        m1 = fmaf(w1.x, sb1[0], m1); m1 = fmaf(w1.y, sb1[1], m1);
        m1 = fmaf(w1.z, sb1[2], m1); m1 = fmaf(w1.w, sb1[3], m1);
        m0 *= pk.x;
        m1 *= pk.y;
        float re = pk.z * m0 - pk.w * m1;
        float im = pk.z * m1 - pk.w * m0;
        sum += sqrtf(fmaf(re, re, fmaf(im, im, EPSC)));
        pk = pkn;
    }
    sum = block_reduce_256(sum, sh);
    if (t == 0) g_magpart[b * 16 + blockIdx.x] = sum;
}

// ---------------------------------------------------------------------------
// Kernel 4: final output, inline scale computation. grid (16, 64), 256 thr.
// ---------------------------------------------------------------------------
__global__ void __launch_bounds__(256)
k_final(const float* __restrict__ conv_w, const float* __restrict__ conv_b,
        float* __restrict__ out)
{
    __shared__ float4 wa4[16][4];
    __shared__ float  s_scale[4], s_weff[4], s_beff;

    const int b  = blockIdx.y;
    const int i0 = blockIdx.x * 16;
    const int t  = threadIdx.x;

    // inline scales for k=0..3
    if (t < 128) {
        int k = t >> 5, q = t & 31;
        float s = g_abs[(k * 32 + q) * 64 + b];
#pragma unroll
        for (int o = 16; o > 0; o >>= 1) s += __shfl_xor_sync(0xFFFFFFFFu, s, o);
        if (q == 0) s_scale[k] = rsqrtf(s * (1.0f / 2048.0f) + EPSC);
    } else if (t < 132) {
        int r = t - 128;
        float w = 0.f;
#pragma unroll
        for (int i = 0; i < RDIM; i++) w += conv_w[i * RDIM + r];
        s_weff[r] = w;
    } else if (t == 132) {
        float bs = 0.f;
#pragma unroll
        for (int i = 0; i < RDIM; i++) bs += conv_b[i];
        s_beff = bs;
    }
    __syncthreads();

    {
        int k = t >> 6, r = (t >> 4) & 3, il = t & 15;
        reinterpret_cast<float*>(wa4)[il * 16 + k * 4 + r] =
            s_weff[r] * s_scale[k]
            * g_mod[(size_t)b * FFDIM + k * 2048 + r * 512 + (i0 + il)];
    }

    float sbv[4][4];
#pragma unroll
    for (int k = 0; k < 4; k++) {
        float sc = s_scale[k];
#pragma unroll
        for (int r = 0; r < 4; r++)
            sbv[k][r] = sc * g_mod[(size_t)b * FFDIM + k * 2048 + r * 512 + HDIM + t];
    }
    __syncthreads();

    float msum = 0.f;
#pragma unroll
    for (int q = 0; q < 16; q++) msum += g_magpart[b * 16 + q];
    const float inv = rsqrtf(msum * (1.0f / 65536.0f) + EPSC);
    const float be = s_beff;

    float4 p1 = g_pkf1[(i0 << 8) + t];
    float4 p2 = g_pkf2[(i0 << 8) + t];
#pragma unroll
    for (int il = 0; il < 16; il++) {
        float4 p1n, p2n;
        if (il < 15) {
            const int pixn = ((i0 + il + 1) << 8) + t;
            p1n = g_pkf1[pixn];
            p2n = g_pkf2[pixn];
        }
        const int pix = ((i0 + il) << 8) + t;
        float m[4];
#pragma unroll
        for (int k = 0; k < 4; k++) {
            float4 wk = wa4[il][k];
            float acc = be;
            acc = fmaf(wk.x, sbv[k][0], acc);
            acc = fmaf(wk.y, sbv[k][1], acc);
            acc = fmaf(wk.z, sbv[k][2], acc);
            acc = fmaf(wk.w, sbv[k][3], acc);
            m[k] = acc;
        }
        m[0] *= p1.x; m[1] *= p1.y; m[2] *= p1.z; m[3] *= p1.w;
        float re = p2.z * m[0] - p2.w * m[1];
        float im = p2.z * m[1] - p2.w * m[0];
        float mwre = fmaf(re, inv, p2.x);
        float mwim = fmaf(im, inv, p2.y);
        float den = sqrtf(fmaf(m[2], m[2], fmaf(m[3], m[3], EPSC)));
        out[((size_t)b << 16) + pix] =
            __fdividef(fmaf(mwre, m[2], mwim * m[3]), den);
        p1 = p1n; p2 = p2n;
    }
}

// ---------------------------------------------------------------------------
// Launch: 4 kernels total
// ---------------------------------------------------------------------------
extern "C" void kernel_launch(void* const* d_in, const int* in_sizes, int n_in,
                              void* d_out, int out_size)
{
    const float* x      = (const float*)d_in[0];
    const float* Wt     = (const float*)d_in[1];
    const float* Wg     = (const float*)d_in[2];
    const float* ws     = (const float*)d_in[3];
    const float* wm     = (const float*)d_in[4];
    const float* conv_w = (const float*)d_in[5];
    const float* conv_b = (const float*)d_in[6];
    float* out = (float*)d_out;

    cudaFuncSetAttribute(k_gemm_mma,
                         cudaFuncAttributeMaxDynamicSharedMemorySize,
                         GEMM_SMEM_BYTES);

    k_pre<<<320, 256>>>(x, ws, wm);
    k_gemm_mma<<<FFDIM / 64, 256, GEMM_SMEM_BYTES>>>(Wt, Wg);
    k_mag<<<dim3(16, BATCH), 256>>>(conv_w, conv_b);
    k_final<<<dim3(16, BATCH), 256>>>(conv_w, conv_b, out);
}